// round 12
// baseline (speedup 1.0000x reference)
#include <cuda_runtime.h>
#include <cuda_fp16.h>
#include <math.h>

#define BB   4
#define SS   1024
#define HIDN 768
#define AHN  384
#define NH   6
#define DDIM 64
#define KSZ  9
#define RPAD 4
#define NROWS (BB*SS)   /* 4096 */
#define TI   8          /* query rows per attention block */
#define HPITCH 40       /* smem half pitch for hgemm tiles */
#define TPF  1096       /* attn score-row pitch (floats), mod 32 == 8 */

// ---------------- scratch (static device globals: allocation-free) ----------
__device__ float g_mq [NROWS*AHN];
__device__ float g_co [NROWS*AHN];
__device__ float g_mkc[NROWS*AHN];
__device__ float g_tdsm[BB*SS];
// half-precision staging
__device__ __half g_Qh [NROWS*HIDN];
__device__ __half g_Kh [NROWS*HIDN];
__device__ __half g_Vh [NROWS*HIDN];
__device__ __half g_dwh[NROWS*HIDN];
__device__ __half g_WqT[AHN*HIDN];   // (N,K) layouts
__device__ __half g_WkT[AHN*HIDN];
__device__ __half g_WvT[AHN*HIDN];
__device__ __half g_coT[AHN*HIDN];
__device__ __half g_pwh[AHN*HIDN];
// half projection outputs for attention
__device__ __half g_mqh[NROWS*AHN];
__device__ __half g_mkh[NROWS*AHN];
__device__ __half g_mvh[NROWS*AHN];

struct JobsH {
    const __half* A[5];
    const __half* B[5];   // (N, K) row-major half
    const float*  bias[5];
    float*        C[5];   // fp32 out (may be null)
    __half*       Ch[5];  // half out (may be null)
};
struct PrepArgs {
    const float *Q, *K, *V, *pw;          // converts
    __half *Qh, *Kh, *Vh, *pwh;
    const float *Wq, *Wk, *Wv, *coW;      // transposes
    __half *WqT, *WkT, *WvT, *coT;
    const float *dw_w;                    // dwconv
    __half *dwh;
    const float *td;                      // tdsm
    const int *mask;
    float *tdsm;
};

// ---------------- PTX helpers ------------------------------------------------
__device__ __forceinline__ void ldsm_x4(unsigned& r0, unsigned& r1,
                                        unsigned& r2, unsigned& r3, unsigned addr) {
    asm volatile("ldmatrix.sync.aligned.m8n8.x4.shared.b16 {%0,%1,%2,%3}, [%4];"
                 : "=r"(r0), "=r"(r1), "=r"(r2), "=r"(r3) : "r"(addr));
}
__device__ __forceinline__ void ldsm_x2t(unsigned& r0, unsigned& r1, unsigned addr) {
    asm volatile("ldmatrix.sync.aligned.m8n8.x2.trans.shared.b16 {%0,%1}, [%2];"
                 : "=r"(r0), "=r"(r1) : "r"(addr));
}
__device__ __forceinline__ void cp_async16(unsigned saddr, const void* gaddr) {
    asm volatile("cp.async.cg.shared.global [%0], [%1], 16;"
                 :: "r"(saddr), "l"(gaddr));
}
__device__ __forceinline__ void cp_commit() {
    asm volatile("cp.async.commit_group;" ::: "memory");
}
__device__ __forceinline__ void cp_wait1() {
    asm volatile("cp.async.wait_group 1;" ::: "memory");
}
__device__ __forceinline__ unsigned packh2(float x, float y) {
    __half2 h = __floats2half2_rn(x, y);
    return *(unsigned*)&h;
}

// ---------------- prep uber-kernel: converts + transposes + dwconv + tdsm ---
__global__ __launch_bounds__(256)
void prep_kernel(PrepArgs a) {
    __shared__ float sh[1160];
    const int blk = blockIdx.x;
    const int tid = threadIdx.x;

    if (blk < 9504) {                      // ---- converts ----
        const float* in; __half* out; int base;
        if      (blk < 3072) { in = a.Q;  out = a.Qh;  base = 0; }
        else if (blk < 6144) { in = a.K;  out = a.Kh;  base = 3072; }
        else if (blk < 9216) { in = a.V;  out = a.Vh;  base = 6144; }
        else                 { in = a.pw; out = a.pwh; base = 9216; }
        int i = (blk - base) * 256 + tid;
        float4 v = ((const float4*)in)[i];
        __half2* o = (__half2*)out;
        o[2 * i]     = __floats2half2_rn(v.x, v.y);
        o[2 * i + 1] = __floats2half2_rn(v.z, v.w);
    } else if (blk < 10656) {              // ---- weight transposes ----
        int e = blk - 9504;
        int zt = e / 288, rem = e % 288;
        const float* in; __half* out;
        if      (zt == 0) { in = a.Wq;  out = a.WqT; }
        else if (zt == 1) { in = a.Wk;  out = a.WkT; }
        else if (zt == 2) { in = a.Wv;  out = a.WvT; }
        else              { in = a.coW; out = a.coT; }
        int c0 = (rem % (AHN / 32)) * 32, r0 = (rem / (AHN / 32)) * 32;
        int tx = tid & 31, ty = tid >> 5;
#pragma unroll
        for (int l = 0; l < 4; l++)
            sh[(ty + 8 * l) * 33 + tx] = in[(size_t)(r0 + ty + 8 * l) * AHN + c0 + tx];
        __syncthreads();
#pragma unroll
        for (int l = 0; l < 4; l++)
            out[(size_t)(c0 + ty + 8 * l) * HIDN + r0 + tx] =
                __float2half_rn(sh[tx * 33 + ty + 8 * l]);
    } else if (blk < 22944) {              // ---- depthwise conv ----
        int e = (blk - 10656) * 256 + tid;
        int c = e % HIDN;
        int bs = e / HIDN;
        int s = bs % SS, b = bs / SS;
        float acc = 0.f;
#pragma unroll
        for (int t = 0; t < KSZ; t++) {
            int sp = s + t - RPAD;
            if (sp >= 0 && sp < SS)
                acc += a.K[((size_t)b * SS + sp) * HIDN + c] * a.dw_w[c * KSZ + t];
        }
        a.dwh[e] = __float2half_rn(acc);
    } else {                               // ---- tdsm ----
        int b = blk - 22944;
        int lane = tid & 31, wid = tid >> 5;
        float* buf = sh;
        float* red = sh + 1024;
        float ss = 0.f;
        for (int j = tid; j < SS; j += 256) { float v = a.td[b * SS + j]; ss += v * v; }
#pragma unroll
        for (int o = 16; o > 0; o >>= 1) ss += __shfl_xor_sync(0xffffffffu, ss, o);
        if (lane == 0) red[wid] = ss;
        __syncthreads();
        float tot = 0.f;
#pragma unroll
        for (int w = 0; w < 8; w++) tot += red[w];
        float nrm = fmaxf(sqrtf(tot), 1e-12f);
        __syncthreads();
        float mx = -3.4e38f;
        for (int j = tid; j < SS; j += 256) {
            float v = a.mask[b * SS + j] ? a.td[b * SS + j] / nrm : -1e4f;
            buf[j] = v;
            mx = fmaxf(mx, v);
        }
#pragma unroll
        for (int o = 16; o > 0; o >>= 1) mx = fmaxf(mx, __shfl_xor_sync(0xffffffffu, mx, o));
        if (lane == 0) red[wid] = mx;
        __syncthreads();
        float bmx = red[0];
#pragma unroll
        for (int w = 1; w < 8; w++) bmx = fmaxf(bmx, red[w]);
        __syncthreads();
        float sum = 0.f;
        for (int j = tid; j < SS; j += 256) {
            float e = expf(buf[j] - bmx);
            buf[j] = e;
            sum += e;
        }
#pragma unroll
        for (int o = 16; o > 0; o >>= 1) sum += __shfl_xor_sync(0xffffffffu, sum, o);
        if (lane == 0) red[wid] = sum;
        __syncthreads();
        float bsum = 0.f;
#pragma unroll
        for (int w = 0; w < 8; w++) bsum += red[w];
        float inv = 1.f / bsum;
        __syncthreads();
        for (int j = tid; j < SS; j += 256) a.tdsm[b * SS + j] = buf[j] * inv;
    }
}

// ---------------- HGEMM: cp.async 3-stage, ldmatrix, 128x128 tile -----------
__global__ __launch_bounds__(256)
void hgemm(JobsH jobs, int M, int N, int K) {
    extern __shared__ __align__(16) __half hsm[];
    __half* Asm = hsm;                       // 3 stages x 128*HPITCH
    __half* Bsm = hsm + 3 * 128 * HPITCH;
    const __half* __restrict__ A    = jobs.A[blockIdx.z];
    const __half* __restrict__ Bm   = jobs.B[blockIdx.z];
    const float*  __restrict__ bias = jobs.bias[blockIdx.z];
    float* __restrict__        C    = jobs.C[blockIdx.z];
    __half* __restrict__       Ch   = jobs.Ch[blockIdx.z];

    const int tid = threadIdx.x, lane = tid & 31, wid = tid >> 5;
    const int wm = wid >> 2, wn = wid & 3;
    const int bm = blockIdx.y * 128, bn = blockIdx.x * 128;
    const int lrow = tid >> 1, lq = tid & 1;

    const int i8 = lane & 7, sel = lane >> 3;
    const int selr = (sel & 1) * 8, selc = (sel >> 1) * 8;
    const unsigned asmBase = (unsigned)__cvta_generic_to_shared(Asm);
    const unsigned bsmBase = (unsigned)__cvta_generic_to_shared(Bsm);
    const unsigned bufB = 128 * HPITCH * 2;

    float D[4][4][4] = {};
    const int nT = K / 32;

    const __half* gA = &A[(size_t)(bm + lrow) * K + lq * 16];
    const __half* gB = &Bm[(size_t)(bn + lrow) * K + lq * 16];
    const unsigned sA = asmBase + (lrow * HPITCH + lq * 16) * 2;
    const unsigned sB = bsmBase + (lrow * HPITCH + lq * 16) * 2;

#pragma unroll
    for (int st = 0; st < 2; st++) {
        cp_async16(sA + st * bufB, gA + st * 32);
        cp_async16(sA + st * bufB + 16, gA + st * 32 + 8);
        cp_async16(sB + st * bufB, gB + st * 32);
        cp_async16(sB + st * bufB + 16, gB + st * 32 + 8);
        cp_commit();
    }

    const int r = lane >> 2, c2 = (lane & 3) * 2;

    for (int kt = 0; kt < nT; kt++) {
        cp_wait1();
        __syncthreads();
        const int cb = kt % 3;
        const unsigned abuf = asmBase + cb * bufB;
        const unsigned bbuf = bsmBase + cb * bufB;
#pragma unroll
        for (int kk = 0; kk < 32; kk += 16) {
            unsigned a[4][4], bfr[2][4];
#pragma unroll
            for (int mf = 0; mf < 4; mf++) {
                int row = wm * 64 + mf * 16 + i8 + selr;
                ldsm_x4(a[mf][0], a[mf][1], a[mf][2], a[mf][3],
                        abuf + (row * HPITCH + kk + selc) * 2);
            }
#pragma unroll
            for (int np = 0; np < 2; np++) {
                int row = wn * 32 + np * 16 + i8 + selr;
                ldsm_x4(bfr[np][0], bfr[np][1], bfr[np][2], bfr[np][3],
                        bbuf + (row * HPITCH + kk + selc) * 2);
            }
#pragma unroll
            for (int mf = 0; mf < 4; mf++)
#pragma unroll
                for (int nf = 0; nf < 4; nf++) {
                    int np = nf >> 1, odd = nf & 1;
                    unsigned b0 = bfr[np][odd];
                    unsigned b1 = bfr[np][odd + 2];
                    float* d = D[mf][nf];
                    asm volatile(
                        "mma.sync.aligned.m16n8k16.row.col.f32.f16.f16.f32 "
                        "{%0,%1,%2,%3}, {%4,%5,%6,%7}, {%8,%9}, {%0,%1,%2,%3};"
                        : "+f"(d[0]), "+f"(d[1]), "+f"(d[2]), "+f"(d[3])
                        : "r"(a[mf][0]), "r"(a[mf][1]), "r"(a[mf][2]), "r"(a[mf][3]),
                          "r"(b0), "r"(b1));
                }
        }
        if (kt + 2 < nT) {
            const int st = (kt + 2) % 3;
            const int k0 = (kt + 2) * 32;
            cp_async16(sA + st * bufB, gA + k0);
            cp_async16(sA + st * bufB + 16, gA + k0 + 8);
            cp_async16(sB + st * bufB, gB + k0);
            cp_async16(sB + st * bufB + 16, gB + k0 + 8);
        }
        cp_commit();
    }

#pragma unroll
    for (int mf = 0; mf < 4; mf++) {
        int row0 = bm + wm * 64 + mf * 16 + r;
#pragma unroll
        for (int nf = 0; nf < 4; nf++) {
            int coln = bn + wn * 32 + nf * 8 + c2;
            float bx = 0.f, by = 0.f;
            if (bias) { bx = bias[coln]; by = bias[coln + 1]; }
            float v0 = D[mf][nf][0] + bx, v1 = D[mf][nf][1] + by;
            float v2 = D[mf][nf][2] + bx, v3 = D[mf][nf][3] + by;
            if (C) {
                *(float2*)&C[(size_t)row0 * N + coln]       = make_float2(v0, v1);
                *(float2*)&C[(size_t)(row0 + 8) * N + coln] = make_float2(v2, v3);
            }
            if (Ch) {
                *(__half2*)&Ch[(size_t)row0 * N + coln]       = __floats2half2_rn(v0, v1);
                *(__half2*)&Ch[(size_t)(row0 + 8) * N + coln] = __floats2half2_rn(v2, v3);
            }
        }
    }
}

// ---------------- fused ck GEMM -> softmax -> dynamic-span conv out ---------
// 16 rows per block -> 256 blocks (2x occupancy vs 32-row version)
__global__ __launch_bounds__(256)
void ckconv(const float* __restrict__ mkc, const float* __restrict__ mq,
            const float* __restrict__ Bm, const float* __restrict__ bias,
            const float* __restrict__ co, float* __restrict__ out) {
    __shared__ float As[16][17];
    __shared__ float Bs[16][64];
    __shared__ float Cs[16][56];
    const int tid = threadIdx.x;
    const int tx = tid & 15, ty = tid >> 4;    // col group, row
    const int bm = blockIdx.x * 16;
    const int NOUT = NH * KSZ;   // 54
    float acc[4] = {};
    for (int k0 = 0; k0 < AHN; k0 += 16) {
        {
            int m = tid >> 4, k = tid & 15;
            size_t e = (size_t)(bm + m) * AHN + k0 + k;
            As[k][m] = mkc[e] * mq[e];
        }
#pragma unroll
        for (int l = 0; l < 4; l++) {
            int idx = tid + 256 * l;
            int k = idx >> 6, n = idx & 63;
            Bs[k][n] = (n < NOUT) ? Bm[(size_t)(k0 + k) * NOUT + n] : 0.f;
        }
        __syncthreads();
#pragma unroll
        for (int k = 0; k < 16; k++) {
            float a = As[k][ty];
            float4 bv = *(const float4*)&Bs[k][tx * 4];
            acc[0] += a * bv.x;
            acc[1] += a * bv.y;
            acc[2] += a * bv.z;
            acc[3] += a * bv.w;
        }
        __syncthreads();
    }
#pragma unroll
    for (int v = 0; v < 4; v++) {
        int n = tx * 4 + v;
        if (n < NOUT) Cs[ty][n] = acc[v] + bias[n];
    }
    __syncthreads();
    if (tid < 16 * NH) {
        int row = tid / NH, h = tid % NH;
        float* p = &Cs[row][h * KSZ];
        float mx = p[0];
#pragma unroll
        for (int t = 1; t < KSZ; t++) mx = fmaxf(mx, p[t]);
        float e[KSZ]; float s = 0.f;
#pragma unroll
        for (int t = 0; t < KSZ; t++) { e[t] = __expf(p[t] - mx); s += e[t]; }
        float inv = 1.f / s;
#pragma unroll
        for (int t = 0; t < KSZ; t++) p[t] = e[t] * inv;
    }
    __syncthreads();
    const int b = bm / SS;
    const int s0 = bm % SS;
    for (int idx = tid; idx < 16 * AHN; idx += 256) {
        int rr = idx / AHN, t = idx % AHN;
        int h = t >> 6;
        int s = s0 + rr;
        float acc2 = 0.f;
#pragma unroll
        for (int k = 0; k < KSZ; k++) {
            int sp = s + k - RPAD;
            if (sp >= 0 && sp < SS)
                acc2 += co[((size_t)b * SS + sp) * AHN + t] * Cs[rr][h * KSZ + k];
        }
        out[(size_t)(bm + rr) * 768 + AHN + t] = acc2;
    }
}

// ---------------- attention: 8 rows/block, 3 blocks/SM ----------------------
// T layout: addr(r, j) = r*TPF + (j>>5)*34 + (j&31); Q zero-padded to 16 rows
__global__ __launch_bounds__(256, 3)
void attn_kernel(const __half* __restrict__ mqh, const __half* __restrict__ mkh,
                 const __half* __restrict__ mvh, const int* __restrict__ mask,
                 const float* __restrict__ tdsm, const float* __restrict__ gammas,
                 float* __restrict__ out) {
    extern __shared__ float sm[];
    float* T   = sm;                       // 8*TPF floats
    float* KV  = T + TI * TPF;             // 4608 floats (Ks/Vs: 128x72 halves)
    float* qsf = KV + 4608;                // 576 floats (Qs: 16x72 halves)
    float* tst = qsf + 576;                // 1056
    __half* Ks = (__half*)KV;
    __half* Vs = (__half*)KV;
    __half* Qs = (__half*)qsf;

    const int i0 = blockIdx.x * TI;
    const int h  = blockIdx.y;
    const int b  = blockIdx.z;
    const int tid = threadIdx.x, lane = tid & 31, w = tid >> 5;
    const int r4 = lane >> 2, c2 = (lane & 3) * 2;
    const int i8 = lane & 7, sel = lane >> 3;
    const int selr = (sel & 1) * 8, selc = (sel >> 1) * 8;
    const unsigned qsB = (unsigned)__cvta_generic_to_shared(Qs);
    const unsigned kvB = (unsigned)__cvta_generic_to_shared(Ks);
    const int* mrow = mask + b * SS;

    // ---- phase 0: Qs (rows 0-7 real, 8-15 zero) + transposed tdsm ----
    if (tid < 64) {
        int r = tid >> 3, dq = tid & 7;
        int4 v = ((const int4*)mqh)[(size_t)(b * SS + i0 + r) * 48 + h * 8 + dq];
        *(int4*)&Qs[r * 72 + dq * 8] = v;
    } else if (tid < 128) {
        int r = tid >> 3, dq = tid & 7;
        *(int4*)&Qs[r * 72 + dq * 8] = make_int4(0, 0, 0, 0);
    }
#pragma unroll
    for (int l = 0; l < 4; l++) {
        int j = tid + 256 * l;
        tst[(j >> 5) * 33 + (j & 31)] = tdsm[b * SS + j];
    }
    __syncthreads();

    // ---- phase 1: scores = Q K^T via ldmatrix + HMMA (rows 0-7 stored) ----
    for (int jt = 0; jt < 8; jt++) {
        const int j0 = jt * 128;
#pragma unroll
        for (int l = 0; l < 4; l++) {
            int e = tid + 256 * l;
            int j = e >> 3, dq = e & 7;
            int4 v = ((const int4*)mkh)[(size_t)(b * SS + j0 + j) * 48 + h * 8 + dq];
            *(int4*)&Ks[j * 72 + dq * 8] = v;
        }
        __syncthreads();
        float acc[2][4] = {};
#pragma unroll
        for (int kc = 0; kc < 4; kc++) {
            const int kk = kc * 16;
            unsigned a0, a1, a2, a3, b0, b1, b2, b3;
            ldsm_x4(a0, a1, a2, a3, qsB + ((i8 + selr) * 72 + kk + selc) * 2);
            ldsm_x4(b0, b1, b2, b3, kvB + ((16 * w + i8 + selr) * 72 + kk + selc) * 2);
            asm volatile(
                "mma.sync.aligned.m16n8k16.row.col.f32.f16.f16.f32 "
                "{%0,%1,%2,%3}, {%4,%5,%6,%7}, {%8,%9}, {%0,%1,%2,%3};"
                : "+f"(acc[0][0]), "+f"(acc[0][1]), "+f"(acc[0][2]), "+f"(acc[0][3])
                : "r"(a0), "r"(a1), "r"(a2), "r"(a3), "r"(b0), "r"(b2));
            asm volatile(
                "mma.sync.aligned.m16n8k16.row.col.f32.f16.f16.f32 "
                "{%0,%1,%2,%3}, {%4,%5,%6,%7}, {%8,%9}, {%0,%1,%2,%3};"
                : "+f"(acc[1][0]), "+f"(acc[1][1]), "+f"(acc[1][2]), "+f"(acc[1][3])
                : "r"(a0), "r"(a1), "r"(a2), "r"(a3), "r"(b1), "r"(b3));
        }
#pragma unroll
        for (int nf = 0; nf < 2; nf++) {
            int j = j0 + 16 * w + 8 * nf + c2;
            int base = (j >> 5) * 34 + (j & 31);
            int m0 = mrow[j], m1 = mrow[j + 1];
            T[r4 * TPF + base]     = m0 ? acc[nf][0] * 0.125f : -1e8f;
            T[r4 * TPF + base + 1] = m1 ? acc[nf][1] * 0.125f : -1e8f;
        }
        __syncthreads();
    }

    // ---- phase 2: warp w owns row w ----
    {
        float gm = gammas[h];
        float gamma = -((gm > 20.f) ? gm : log1pf(expf(gm)));
        const int r = w;
        const int i = i0 + r;
        float* Trow = T + r * TPF + lane * 34;   // lane-private 32 cols
        float mx = -3.4e38f;
#pragma unroll
        for (int t = 0; t < 32; t++) mx = fmaxf(mx, Trow[t]);
#pragma unroll
        for (int o = 16; o; o >>= 1) mx = fmaxf(mx, __shfl_xor_sync(0xffffffffu, mx, o));
        float p[32];
        float sum = 0.f;
#pragma unroll
        for (int t = 0; t < 32; t++) {
            float sv = Trow[t];
            p[t] = (sv > -1e7f) ? __expf(sv - mx) : 0.f;
            sum += p[t];
        }
#pragma unroll
        for (int o = 16; o; o >>= 1) sum += __shfl_xor_sync(0xffffffffu, sum, o);
        float inv = 1.f / sum;
        float run = 0.f;
#pragma unroll
        for (int t = 0; t < 32; t++) { run += p[t] * inv; p[t] = run; }
        float tot = run;
        float ex = tot;
#pragma unroll
        for (int d = 1; d < 32; d <<= 1) {
            float y = __shfl_up_sync(0xffffffffu, ex, d);
            if (lane >= d) ex += y;
        }
        float total = __shfl_sync(0xffffffffu, ex, 31);
        float excl = ex - tot;
#pragma unroll
        for (int t = 0; t < 32; t++) {
            float sv = Trow[t];
            if (sv > -1e7f) {
                int j = lane * 32 + t;
                float pos = fabsf((float)(j - i));
                float rem = total - (excl + p[t]);
                float ds = sqrtf(fmaxf(rem * pos, 0.f));
                float te = fmaxf(__expf(ds * gamma), 1e-5f);
                if (j < i) te -= tst[lane * 33 + t];
                Trow[t] = sv * te;
            }
        }
        float mx2 = -3.4e38f;
#pragma unroll
        for (int t = 0; t < 32; t++) mx2 = fmaxf(mx2, Trow[t]);
#pragma unroll
        for (int o = 16; o; o >>= 1) mx2 = fmaxf(mx2, __shfl_xor_sync(0xffffffffu, mx2, o));
        float sum2 = 0.f;
#pragma unroll
        for (int t = 0; t < 32; t++) {
            float sv = Trow[t];
            p[t] = (sv > -1e7f) ? __expf(sv - mx2) : 0.f;
            sum2 += p[t];
        }
#pragma unroll
        for (int o = 16; o; o >>= 1) sum2 += __shfl_xor_sync(0xffffffffu, sum2, o);
        float inv2 = 1.f / sum2;
#pragma unroll
        for (int t = 0; t < 32; t++) Trow[t] = p[t] * inv2;
    }
    __syncthreads();

    // ---- phase 3: ctx = P V ; rows 8-15 of A are zero ----
    float acc[4] = {0.f, 0.f, 0.f, 0.f};
    const int il = lane & 15;
    const float* P0 = T + r4 * TPF;
    for (int jt = 0; jt < 8; jt++) {
        const int j0 = jt * 128;
#pragma unroll
        for (int l = 0; l < 4; l++) {
            int e = tid + 256 * l;
            int j = e >> 3, dq = e & 7;
            int4 v = ((const int4*)mvh)[(size_t)(b * SS + j0 + j) * 48 + h * 8 + dq];
            *(int4*)&Vs[j * 72 + dq * 8] = v;
        }
        __syncthreads();
#pragma unroll
        for (int kc = 0; kc < 8; kc++) {
            const int kl = kc * 16;
            const int jg = j0 + kl + c2;
            const int cb = (jg >> 5) * 34 + (jg & 31);
            float2 v0 = *(const float2*)&P0[cb];
            float2 v2 = *(const float2*)&P0[cb + 8];
            unsigned a0 = packh2(v0.x, v0.y);
            unsigned a2 = packh2(v2.x, v2.y);
            unsigned b0, b1;
            ldsm_x2t(b0, b1, kvB + ((kl + il) * 72 + 8 * w) * 2);
            asm volatile(
                "mma.sync.aligned.m16n8k16.row.col.f32.f16.f16.f32 "
                "{%0,%1,%2,%3}, {%4,%5,%6,%7}, {%8,%9}, {%0,%1,%2,%3};"
                : "+f"(acc[0]), "+f"(acc[1]), "+f"(acc[2]), "+f"(acc[3])
                : "r"(a0), "r"(0u), "r"(a2), "r"(0u), "r"(b0), "r"(b1));
        }
        __syncthreads();
    }
    {
        int dc = h * DDIM + 8 * w + c2;
        size_t o0 = (size_t)(b * SS + i0 + r4) * 768 + dc;
        *(float2*)&out[o0] = make_float2(acc[0], acc[1]);
    }
}

// ---------------- launch ----------------------------------------------------
extern "C" void kernel_launch(void* const* d_in, const int* in_sizes, int n_in,
                              void* d_out, int out_size) {
    const float* Q    = (const float*)d_in[0];
    const float* Kin  = (const float*)d_in[1];
    const float* V    = (const float*)d_in[2];
    const float* td   = (const float*)d_in[3];
    const int*   mask = (const int*)  d_in[4];
    const float* Wq   = (const float*)d_in[5];
    const float* Wk   = (const float*)d_in[6];
    const float* Wv   = (const float*)d_in[7];
    const float* dw_w = (const float*)d_in[8];
    const float* pw_w = (const float*)d_in[9];
    const float* sep_b= (const float*)d_in[10];
    const float* ck_W = (const float*)d_in[11];
    const float* ck_b = (const float*)d_in[12];
    const float* co_W = (const float*)d_in[13];
    const float* co_b = (const float*)d_in[14];
    const float* gammas=(const float*)d_in[15];
    float* out = (float*)d_out;

    float *mq, *co, *mkc, *tdsm;
    __half *Qh, *Kh, *Vh, *dwh, *WqT, *WkT, *WvT, *coT, *pwh, *mqh, *mkh, *mvh;
    cudaGetSymbolAddress((void**)&mq,  g_mq);
    cudaGetSymbolAddress((void**)&co,  g_co);
    cudaGetSymbolAddress((void**)&mkc, g_mkc);
    cudaGetSymbolAddress((void**)&tdsm,g_tdsm);
    cudaGetSymbolAddress((void**)&Qh,  g_Qh);
    cudaGetSymbolAddress((void**)&Kh,  g_Kh);
    cudaGetSymbolAddress((void**)&Vh,  g_Vh);
    cudaGetSymbolAddress((void**)&dwh, g_dwh);
    cudaGetSymbolAddress((void**)&WqT, g_WqT);
    cudaGetSymbolAddress((void**)&WkT, g_WkT);
    cudaGetSymbolAddress((void**)&WvT, g_WvT);
    cudaGetSymbolAddress((void**)&coT, g_coT);
    cudaGetSymbolAddress((void**)&pwh, g_pwh);
    cudaGetSymbolAddress((void**)&mqh, g_mqh);
    cudaGetSymbolAddress((void**)&mkh, g_mkh);
    cudaGetSymbolAddress((void**)&mvh, g_mvh);

    static int smem_set = 0;
    const int attn_smem = (TI * TPF + 4608 + 576 + 1056) * 4;   // 60032 B
    const int hgemm_smem = 3 * 2 * 128 * HPITCH * 2;            // 61440 B
    if (!smem_set) {
        cudaFuncSetAttribute(attn_kernel, cudaFuncAttributeMaxDynamicSharedMemorySize,
                             attn_smem);
        cudaFuncSetAttribute(hgemm, cudaFuncAttributeMaxDynamicSharedMemorySize,
                             hgemm_smem);
        smem_set = 1;
    }

    // ---- prep: converts + transposes + dwconv + tdsm in one launch ----
    PrepArgs pa;
    pa.Q = Q; pa.K = Kin; pa.V = V; pa.pw = pw_w;
    pa.Qh = Qh; pa.Kh = Kh; pa.Vh = Vh; pa.pwh = pwh;
    pa.Wq = Wq; pa.Wk = Wk; pa.Wv = Wv; pa.coW = co_W;
    pa.WqT = WqT; pa.WkT = WkT; pa.WvT = WvT; pa.coT = coT;
    pa.dw_w = dw_w; pa.dwh = dwh;
    pa.td = td; pa.mask = mask; pa.tdsm = tdsm;
    prep_kernel<<<22948, 256>>>(pa);

    // ---- 5 big GEMMs, one launch ----
    JobsH jh;
    jh.A[0] = Qh;  jh.B[0] = WqT; jh.bias[0] = nullptr; jh.C[0] = mq;     jh.Ch[0] = mqh;
    jh.A[1] = Kh;  jh.B[1] = WkT; jh.bias[1] = nullptr; jh.C[1] = nullptr;jh.Ch[1] = mkh;
    jh.A[2] = Vh;  jh.B[2] = WvT; jh.bias[2] = nullptr; jh.C[2] = nullptr;jh.Ch[2] = mvh;
    jh.A[3] = Vh;  jh.B[3] = coT; jh.bias[3] = co_b;    jh.C[3] = co;     jh.Ch[3] = nullptr;
    jh.A[4] = dwh; jh.B[4] = pwh; jh.bias[4] = sep_b;   jh.C[4] = mkc;    jh.Ch[4] = nullptr;
    hgemm<<<dim3(AHN / 128, NROWS / 128, 5), 256, hgemm_smem>>>(jh, NROWS, AHN, HIDN);

    attn_kernel<<<dim3(SS / TI, NH, BB), 256, attn_smem>>>(mqh, mkh, mvh, mask, tdsm,
                                                           gammas, out);
    ckconv<<<NROWS / 16, 256>>>(mkc, mq, ck_W, ck_b, co, out);
}

// round 13
// speedup vs baseline: 1.0963x; 1.0963x over previous
#include <cuda_runtime.h>
#include <cuda_fp16.h>
#include <math.h>

#define BB   4
#define SS   1024
#define HIDN 768
#define AHN  384
#define NH   6
#define DDIM 64
#define KSZ  9
#define RPAD 4
#define NROWS (BB*SS)   /* 4096 */
#define TI   16         /* query rows per attention block */
#define HPITCH 40       /* smem half pitch for hgemm tiles */
#define TPF  1096       /* attn score-row pitch (floats), mod 32 == 8 */

// ---------------- scratch (static device globals: allocation-free) ----------
__device__ float g_mq [NROWS*AHN];
__device__ float g_co [NROWS*AHN];
__device__ float g_mkc[NROWS*AHN];
__device__ float g_tdsm[BB*SS];
// half-precision staging
__device__ __half g_Qh [NROWS*HIDN];
__device__ __half g_Kh [NROWS*HIDN];
__device__ __half g_Vh [NROWS*HIDN];
__device__ __half g_dwh[NROWS*HIDN];
__device__ __half g_WqT[AHN*HIDN];   // (N,K) layouts
__device__ __half g_WkT[AHN*HIDN];
__device__ __half g_WvT[AHN*HIDN];
__device__ __half g_coT[AHN*HIDN];
__device__ __half g_pwh[AHN*HIDN];
// half projection outputs for attention
__device__ __half g_mqh[NROWS*AHN];
__device__ __half g_mkh[NROWS*AHN];
__device__ __half g_mvh[NROWS*AHN];

struct JobsH {
    const __half* A[5];
    const __half* B[5];   // (N, K) row-major half
    const float*  bias[5];
    float*        C[5];   // fp32 out (may be null)
    __half*       Ch[5];  // half out (may be null)
};
struct PrepArgs {
    const float *Q, *K, *V, *pw;          // converts
    __half *Qh, *Kh, *Vh, *pwh;
    const float *Wq, *Wk, *Wv, *coW;      // transposes
    __half *WqT, *WkT, *WvT, *coT;
    const float *dw_w;                    // dwconv
    __half *dwh;
    const float *td;                      // tdsm
    const int *mask;
    float *tdsm;
};

// ---------------- PTX helpers ------------------------------------------------
__device__ __forceinline__ void ldsm_x4(unsigned& r0, unsigned& r1,
                                        unsigned& r2, unsigned& r3, unsigned addr) {
    asm volatile("ldmatrix.sync.aligned.m8n8.x4.shared.b16 {%0,%1,%2,%3}, [%4];"
                 : "=r"(r0), "=r"(r1), "=r"(r2), "=r"(r3) : "r"(addr));
}
__device__ __forceinline__ void ldsm_x2t(unsigned& r0, unsigned& r1, unsigned addr) {
    asm volatile("ldmatrix.sync.aligned.m8n8.x2.trans.shared.b16 {%0,%1}, [%2];"
                 : "=r"(r0), "=r"(r1) : "r"(addr));
}
__device__ __forceinline__ void cp_async16(unsigned saddr, const void* gaddr) {
    asm volatile("cp.async.cg.shared.global [%0], [%1], 16;"
                 :: "r"(saddr), "l"(gaddr));
}
__device__ __forceinline__ void cp_commit() {
    asm volatile("cp.async.commit_group;" ::: "memory");
}
__device__ __forceinline__ void cp_wait1() {
    asm volatile("cp.async.wait_group 1;" ::: "memory");
}
__device__ __forceinline__ unsigned packh2(float x, float y) {
    __half2 h = __floats2half2_rn(x, y);
    return *(unsigned*)&h;
}

// ---------------- prep uber-kernel: converts + transposes + dwconv + tdsm ---
__global__ __launch_bounds__(256)
void prep_kernel(PrepArgs a) {
    __shared__ float sh[1160];
    const int blk = blockIdx.x;
    const int tid = threadIdx.x;

    if (blk < 9504) {                      // ---- converts ----
        const float* in; __half* out; int base;
        if      (blk < 3072) { in = a.Q;  out = a.Qh;  base = 0; }
        else if (blk < 6144) { in = a.K;  out = a.Kh;  base = 3072; }
        else if (blk < 9216) { in = a.V;  out = a.Vh;  base = 6144; }
        else                 { in = a.pw; out = a.pwh; base = 9216; }
        int i = (blk - base) * 256 + tid;
        float4 v = ((const float4*)in)[i];
        __half2* o = (__half2*)out;
        o[2 * i]     = __floats2half2_rn(v.x, v.y);
        o[2 * i + 1] = __floats2half2_rn(v.z, v.w);
    } else if (blk < 10656) {              // ---- weight transposes ----
        int e = blk - 9504;
        int zt = e / 288, rem = e % 288;
        const float* in; __half* out;
        if      (zt == 0) { in = a.Wq;  out = a.WqT; }
        else if (zt == 1) { in = a.Wk;  out = a.WkT; }
        else if (zt == 2) { in = a.Wv;  out = a.WvT; }
        else              { in = a.coW; out = a.coT; }
        int c0 = (rem % (AHN / 32)) * 32, r0 = (rem / (AHN / 32)) * 32;
        int tx = tid & 31, ty = tid >> 5;
#pragma unroll
        for (int l = 0; l < 4; l++)
            sh[(ty + 8 * l) * 33 + tx] = in[(size_t)(r0 + ty + 8 * l) * AHN + c0 + tx];
        __syncthreads();
#pragma unroll
        for (int l = 0; l < 4; l++)
            out[(size_t)(c0 + ty + 8 * l) * HIDN + r0 + tx] =
                __float2half_rn(sh[tx * 33 + ty + 8 * l]);
    } else if (blk < 22944) {              // ---- depthwise conv ----
        int e = (blk - 10656) * 256 + tid;
        int c = e % HIDN;
        int bs = e / HIDN;
        int s = bs % SS, b = bs / SS;
        float acc = 0.f;
#pragma unroll
        for (int t = 0; t < KSZ; t++) {
            int sp = s + t - RPAD;
            if (sp >= 0 && sp < SS)
                acc += a.K[((size_t)b * SS + sp) * HIDN + c] * a.dw_w[c * KSZ + t];
        }
        a.dwh[e] = __float2half_rn(acc);
    } else {                               // ---- tdsm ----
        int b = blk - 22944;
        int lane = tid & 31, wid = tid >> 5;
        float* buf = sh;
        float* red = sh + 1024;
        float ss = 0.f;
        for (int j = tid; j < SS; j += 256) { float v = a.td[b * SS + j]; ss += v * v; }
#pragma unroll
        for (int o = 16; o > 0; o >>= 1) ss += __shfl_xor_sync(0xffffffffu, ss, o);
        if (lane == 0) red[wid] = ss;
        __syncthreads();
        float tot = 0.f;
#pragma unroll
        for (int w = 0; w < 8; w++) tot += red[w];
        float nrm = fmaxf(sqrtf(tot), 1e-12f);
        __syncthreads();
        float mx = -3.4e38f;
        for (int j = tid; j < SS; j += 256) {
            float v = a.mask[b * SS + j] ? a.td[b * SS + j] / nrm : -1e4f;
            buf[j] = v;
            mx = fmaxf(mx, v);
        }
#pragma unroll
        for (int o = 16; o > 0; o >>= 1) mx = fmaxf(mx, __shfl_xor_sync(0xffffffffu, mx, o));
        if (lane == 0) red[wid] = mx;
        __syncthreads();
        float bmx = red[0];
#pragma unroll
        for (int w = 1; w < 8; w++) bmx = fmaxf(bmx, red[w]);
        __syncthreads();
        float sum = 0.f;
        for (int j = tid; j < SS; j += 256) {
            float e = expf(buf[j] - bmx);
            buf[j] = e;
            sum += e;
        }
#pragma unroll
        for (int o = 16; o > 0; o >>= 1) sum += __shfl_xor_sync(0xffffffffu, sum, o);
        if (lane == 0) red[wid] = sum;
        __syncthreads();
        float bsum = 0.f;
#pragma unroll
        for (int w = 0; w < 8; w++) bsum += red[w];
        float inv = 1.f / bsum;
        __syncthreads();
        for (int j = tid; j < SS; j += 256) a.tdsm[b * SS + j] = buf[j] * inv;
    }
}

// ---------------- HGEMM: cp.async 3-stage, ldmatrix, 128x128 tile -----------
__global__ __launch_bounds__(256)
void hgemm(JobsH jobs, int M, int N, int K) {
    extern __shared__ __align__(16) __half hsm[];
    __half* Asm = hsm;                       // 3 stages x 128*HPITCH
    __half* Bsm = hsm + 3 * 128 * HPITCH;
    const __half* __restrict__ A    = jobs.A[blockIdx.z];
    const __half* __restrict__ Bm   = jobs.B[blockIdx.z];
    const float*  __restrict__ bias = jobs.bias[blockIdx.z];
    float* __restrict__        C    = jobs.C[blockIdx.z];
    __half* __restrict__       Ch   = jobs.Ch[blockIdx.z];

    const int tid = threadIdx.x, lane = tid & 31, wid = tid >> 5;
    const int wm = wid >> 2, wn = wid & 3;
    const int bm = blockIdx.y * 128, bn = blockIdx.x * 128;
    const int lrow = tid >> 1, lq = tid & 1;

    const int i8 = lane & 7, sel = lane >> 3;
    const int selr = (sel & 1) * 8, selc = (sel >> 1) * 8;
    const unsigned asmBase = (unsigned)__cvta_generic_to_shared(Asm);
    const unsigned bsmBase = (unsigned)__cvta_generic_to_shared(Bsm);
    const unsigned bufB = 128 * HPITCH * 2;

    float D[4][4][4] = {};
    const int nT = K / 32;

    const __half* gA = &A[(size_t)(bm + lrow) * K + lq * 16];
    const __half* gB = &Bm[(size_t)(bn + lrow) * K + lq * 16];
    const unsigned sA = asmBase + (lrow * HPITCH + lq * 16) * 2;
    const unsigned sB = bsmBase + (lrow * HPITCH + lq * 16) * 2;

#pragma unroll
    for (int st = 0; st < 2; st++) {
        cp_async16(sA + st * bufB, gA + st * 32);
        cp_async16(sA + st * bufB + 16, gA + st * 32 + 8);
        cp_async16(sB + st * bufB, gB + st * 32);
        cp_async16(sB + st * bufB + 16, gB + st * 32 + 8);
        cp_commit();
    }

    const int r = lane >> 2, c2 = (lane & 3) * 2;

    for (int kt = 0; kt < nT; kt++) {
        cp_wait1();
        __syncthreads();
        const int cb = kt % 3;
        const unsigned abuf = asmBase + cb * bufB;
        const unsigned bbuf = bsmBase + cb * bufB;
#pragma unroll
        for (int kk = 0; kk < 32; kk += 16) {
            unsigned a[4][4], bfr[2][4];
#pragma unroll
            for (int mf = 0; mf < 4; mf++) {
                int row = wm * 64 + mf * 16 + i8 + selr;
                ldsm_x4(a[mf][0], a[mf][1], a[mf][2], a[mf][3],
                        abuf + (row * HPITCH + kk + selc) * 2);
            }
#pragma unroll
            for (int np = 0; np < 2; np++) {
                int row = wn * 32 + np * 16 + i8 + selr;
                ldsm_x4(bfr[np][0], bfr[np][1], bfr[np][2], bfr[np][3],
                        bbuf + (row * HPITCH + kk + selc) * 2);
            }
#pragma unroll
            for (int mf = 0; mf < 4; mf++)
#pragma unroll
                for (int nf = 0; nf < 4; nf++) {
                    int np = nf >> 1, odd = nf & 1;
                    unsigned b0 = bfr[np][odd];
                    unsigned b1 = bfr[np][odd + 2];
                    float* d = D[mf][nf];
                    asm volatile(
                        "mma.sync.aligned.m16n8k16.row.col.f32.f16.f16.f32 "
                        "{%0,%1,%2,%3}, {%4,%5,%6,%7}, {%8,%9}, {%0,%1,%2,%3};"
                        : "+f"(d[0]), "+f"(d[1]), "+f"(d[2]), "+f"(d[3])
                        : "r"(a[mf][0]), "r"(a[mf][1]), "r"(a[mf][2]), "r"(a[mf][3]),
                          "r"(b0), "r"(b1));
                }
        }
        if (kt + 2 < nT) {
            const int st = (kt + 2) % 3;
            const int k0 = (kt + 2) * 32;
            cp_async16(sA + st * bufB, gA + k0);
            cp_async16(sA + st * bufB + 16, gA + k0 + 8);
            cp_async16(sB + st * bufB, gB + k0);
            cp_async16(sB + st * bufB + 16, gB + k0 + 8);
        }
        cp_commit();
    }

#pragma unroll
    for (int mf = 0; mf < 4; mf++) {
        int row0 = bm + wm * 64 + mf * 16 + r;
#pragma unroll
        for (int nf = 0; nf < 4; nf++) {
            int coln = bn + wn * 32 + nf * 8 + c2;
            float bx = 0.f, by = 0.f;
            if (bias) { bx = bias[coln]; by = bias[coln + 1]; }
            float v0 = D[mf][nf][0] + bx, v1 = D[mf][nf][1] + by;
            float v2 = D[mf][nf][2] + bx, v3 = D[mf][nf][3] + by;
            if (C) {
                *(float2*)&C[(size_t)row0 * N + coln]       = make_float2(v0, v1);
                *(float2*)&C[(size_t)(row0 + 8) * N + coln] = make_float2(v2, v3);
            }
            if (Ch) {
                *(__half2*)&Ch[(size_t)row0 * N + coln]       = __floats2half2_rn(v0, v1);
                *(__half2*)&Ch[(size_t)(row0 + 8) * N + coln] = __floats2half2_rn(v2, v3);
            }
        }
    }
}

// ---------------- fused ck GEMM -> softmax -> dynamic-span conv out ---------
// 16 rows per block; co window staged in smem (24 rows x 384)
__global__ __launch_bounds__(256)
void ckconv(const float* __restrict__ mkc, const float* __restrict__ mq,
            const float* __restrict__ Bm, const float* __restrict__ bias,
            const float* __restrict__ co, float* __restrict__ out) {
    __shared__ float As[16][17];
    __shared__ float Bs[16][64];
    __shared__ float Cs[16][56];
    __shared__ float Co[24][AHN];
    const int tid = threadIdx.x;
    const int tx = tid & 15, ty = tid >> 4;    // col group, row
    const int bm = blockIdx.x * 16;
    const int NOUT = NH * KSZ;   // 54
    const int b = bm / SS;
    const int s0 = bm % SS;

    // stage co window rows [s0-4, s0+19] (clamped) while doing the GEMM loads
    for (int idx = tid; idx < 24 * (AHN / 4); idx += 256) {
        int rr = idx / (AHN / 4), t4 = idx % (AHN / 4);
        int sp = s0 + rr - RPAD;
        float4 v = make_float4(0.f, 0.f, 0.f, 0.f);
        if (sp >= 0 && sp < SS)
            v = *(const float4*)&co[((size_t)b * SS + sp) * AHN + t4 * 4];
        *(float4*)&Co[rr][t4 * 4] = v;
    }

    float acc[4] = {};
    for (int k0 = 0; k0 < AHN; k0 += 16) {
        {
            int m = tid >> 4, k = tid & 15;
            size_t e = (size_t)(bm + m) * AHN + k0 + k;
            As[k][m] = mkc[e] * mq[e];
        }
#pragma unroll
        for (int l = 0; l < 4; l++) {
            int idx = tid + 256 * l;
            int k = idx >> 6, n = idx & 63;
            Bs[k][n] = (n < NOUT) ? Bm[(size_t)(k0 + k) * NOUT + n] : 0.f;
        }
        __syncthreads();
#pragma unroll
        for (int k = 0; k < 16; k++) {
            float a = As[k][ty];
            float4 bv = *(const float4*)&Bs[k][tx * 4];
            acc[0] += a * bv.x;
            acc[1] += a * bv.y;
            acc[2] += a * bv.z;
            acc[3] += a * bv.w;
        }
        __syncthreads();
    }
#pragma unroll
    for (int v = 0; v < 4; v++) {
        int n = tx * 4 + v;
        if (n < NOUT) Cs[ty][n] = acc[v] + bias[n];
    }
    __syncthreads();
    if (tid < 16 * NH) {
        int row = tid / NH, h = tid % NH;
        float* p = &Cs[row][h * KSZ];
        float mx = p[0];
#pragma unroll
        for (int t = 1; t < KSZ; t++) mx = fmaxf(mx, p[t]);
        float e[KSZ]; float s = 0.f;
#pragma unroll
        for (int t = 0; t < KSZ; t++) { e[t] = __expf(p[t] - mx); s += e[t]; }
        float inv = 1.f / s;
#pragma unroll
        for (int t = 0; t < KSZ; t++) p[t] = e[t] * inv;
    }
    __syncthreads();
    // conv from smem-staged co window: Co row (rr + k) == global s0+rr+k-RPAD
    for (int idx = tid; idx < 16 * AHN; idx += 256) {
        int rr = idx / AHN, t = idx % AHN;
        int h = t >> 6;
        float acc2 = 0.f;
#pragma unroll
        for (int k = 0; k < KSZ; k++)
            acc2 += Co[rr + k][t] * Cs[rr][h * KSZ + k];
        out[(size_t)(bm + rr) * 768 + AHN + t] = acc2;
    }
}

// ---------------- attention: 16 rows/block, fp32 probs (round-11 version) ---
// T layout: addr(r, j) = r*TPF + (j>>5)*34 + (j&31)
__global__ __launch_bounds__(256, 2)
void attn_kernel(const __half* __restrict__ mqh, const __half* __restrict__ mkh,
                 const __half* __restrict__ mvh, const int* __restrict__ mask,
                 const float* __restrict__ tdsm, const float* __restrict__ gammas,
                 float* __restrict__ out) {
    extern __shared__ float sm[];
    float* T   = sm;                       // 16*TPF floats
    float* KV  = T + TI * TPF;             // 4608 floats (Ks/Vs: 128x72 halves)
    float* qsf = KV + 4608;                // 576 floats (Qs)
    float* tst = qsf + 576;                // 1056
    __half* Ks = (__half*)KV;
    __half* Vs = (__half*)KV;
    __half* Qs = (__half*)qsf;

    const int i0 = blockIdx.x * TI;
    const int h  = blockIdx.y;
    const int b  = blockIdx.z;
    const int tid = threadIdx.x, lane = tid & 31, w = tid >> 5;
    const int r4 = lane >> 2, c2 = (lane & 3) * 2;
    const int i8 = lane & 7, sel = lane >> 3;
    const int selr = (sel & 1) * 8, selc = (sel >> 1) * 8;
    const unsigned qsB = (unsigned)__cvta_generic_to_shared(Qs);
    const unsigned kvB = (unsigned)__cvta_generic_to_shared(Ks);
    const int* mrow = mask + b * SS;

    // ---- phase 0: Qs + transposed tdsm ----
    if (tid < 128) {
        int r = tid >> 3, dq = tid & 7;
        int4 v = ((const int4*)mqh)[(size_t)(b * SS + i0 + r) * 48 + h * 8 + dq];
        *(int4*)&Qs[r * 72 + dq * 8] = v;
    }
#pragma unroll
    for (int l = 0; l < 4; l++) {
        int j = tid + 256 * l;
        tst[(j >> 5) * 33 + (j & 31)] = tdsm[b * SS + j];
    }
    __syncthreads();

    // ---- phase 1: scores = Q K^T via ldmatrix + HMMA ----
    for (int jt = 0; jt < 8; jt++) {
        const int j0 = jt * 128;
#pragma unroll
        for (int l = 0; l < 4; l++) {
            int e = tid + 256 * l;
            int j = e >> 3, dq = e & 7;
            int4 v = ((const int4*)mkh)[(size_t)(b * SS + j0 + j) * 48 + h * 8 + dq];
            *(int4*)&Ks[j * 72 + dq * 8] = v;
        }
        __syncthreads();
        float acc[2][4] = {};
#pragma unroll
        for (int kc = 0; kc < 4; kc++) {
            const int kk = kc * 16;
            unsigned a0, a1, a2, a3, b0, b1, b2, b3;
            ldsm_x4(a0, a1, a2, a3, qsB + ((i8 + selr) * 72 + kk + selc) * 2);
            ldsm_x4(b0, b1, b2, b3, kvB + ((16 * w + i8 + selr) * 72 + kk + selc) * 2);
            asm volatile(
                "mma.sync.aligned.m16n8k16.row.col.f32.f16.f16.f32 "
                "{%0,%1,%2,%3}, {%4,%5,%6,%7}, {%8,%9}, {%0,%1,%2,%3};"
                : "+f"(acc[0][0]), "+f"(acc[0][1]), "+f"(acc[0][2]), "+f"(acc[0][3])
                : "r"(a0), "r"(a1), "r"(a2), "r"(a3), "r"(b0), "r"(b2));
            asm volatile(
                "mma.sync.aligned.m16n8k16.row.col.f32.f16.f16.f32 "
                "{%0,%1,%2,%3}, {%4,%5,%6,%7}, {%8,%9}, {%0,%1,%2,%3};"
                : "+f"(acc[1][0]), "+f"(acc[1][1]), "+f"(acc[1][2]), "+f"(acc[1][3])
                : "r"(a0), "r"(a1), "r"(a2), "r"(a3), "r"(b1), "r"(b3));
        }
#pragma unroll
        for (int nf = 0; nf < 2; nf++) {
            int j = j0 + 16 * w + 8 * nf + c2;
            int base = (j >> 5) * 34 + (j & 31);
            int m0 = mrow[j], m1 = mrow[j + 1];
            float s00 = m0 ? acc[nf][0] * 0.125f : -1e8f;
            float s01 = m1 ? acc[nf][1] * 0.125f : -1e8f;
            float s10 = m0 ? acc[nf][2] * 0.125f : -1e8f;
            float s11 = m1 ? acc[nf][3] * 0.125f : -1e8f;
            T[r4 * TPF + base]           = s00;
            T[r4 * TPF + base + 1]       = s01;
            T[(r4 + 8) * TPF + base]     = s10;
            T[(r4 + 8) * TPF + base + 1] = s11;
        }
        __syncthreads();
    }

    // ---- phase 2: per-row softmax -> cumsum -> rescore -> softmax (fp32) ---
    {
        float gm = gammas[h];
        float gamma = -((gm > 20.f) ? gm : log1pf(expf(gm)));
#pragma unroll 1
        for (int rr = 0; rr < 2; rr++) {
            const int r = 2 * w + rr;
            const int i = i0 + r;
            float* Trow = T + r * TPF + lane * 34;   // lane-private 32 cols
            float mx = -3.4e38f;
#pragma unroll
            for (int t = 0; t < 32; t++) mx = fmaxf(mx, Trow[t]);
#pragma unroll
            for (int o = 16; o; o >>= 1) mx = fmaxf(mx, __shfl_xor_sync(0xffffffffu, mx, o));
            float p[32];
            float sum = 0.f;
#pragma unroll
            for (int t = 0; t < 32; t++) {
                float sv = Trow[t];
                p[t] = (sv > -1e7f) ? __expf(sv - mx) : 0.f;
                sum += p[t];
            }
#pragma unroll
            for (int o = 16; o; o >>= 1) sum += __shfl_xor_sync(0xffffffffu, sum, o);
            float inv = 1.f / sum;
            float run = 0.f;
#pragma unroll
            for (int t = 0; t < 32; t++) { run += p[t] * inv; p[t] = run; }
            float tot = run;
            float ex = tot;
#pragma unroll
            for (int d = 1; d < 32; d <<= 1) {
                float y = __shfl_up_sync(0xffffffffu, ex, d);
                if (lane >= d) ex += y;
            }
            float total = __shfl_sync(0xffffffffu, ex, 31);
            float excl = ex - tot;
#pragma unroll
            for (int t = 0; t < 32; t++) {
                float sv = Trow[t];
                if (sv > -1e7f) {
                    int j = lane * 32 + t;
                    float pos = fabsf((float)(j - i));
                    float rem = total - (excl + p[t]);
                    float ds = sqrtf(fmaxf(rem * pos, 0.f));
                    float te = fmaxf(__expf(ds * gamma), 1e-5f);
                    if (j < i) te -= tst[lane * 33 + t];
                    Trow[t] = sv * te;
                }
            }
            float mx2 = -3.4e38f;
#pragma unroll
            for (int t = 0; t < 32; t++) mx2 = fmaxf(mx2, Trow[t]);
#pragma unroll
            for (int o = 16; o; o >>= 1) mx2 = fmaxf(mx2, __shfl_xor_sync(0xffffffffu, mx2, o));
            float sum2 = 0.f;
#pragma unroll
            for (int t = 0; t < 32; t++) {
                float sv = Trow[t];
                p[t] = (sv > -1e7f) ? __expf(sv - mx2) : 0.f;
                sum2 += p[t];
            }
#pragma unroll
            for (int o = 16; o; o >>= 1) sum2 += __shfl_xor_sync(0xffffffffu, sum2, o);
            float inv2 = 1.f / sum2;
#pragma unroll
            for (int t = 0; t < 32; t++) Trow[t] = p[t] * inv2;   // fp32 probs
        }
    }
    __syncthreads();

    // ---- phase 3: ctx = P V ; A frags from fp32 probs via LDS.64 + pack ----
    float acc[4] = {0.f, 0.f, 0.f, 0.f};
    const int il = lane & 15;
    const float* P0 = T + r4 * TPF;
    const float* P8 = T + (r4 + 8) * TPF;
    for (int jt = 0; jt < 8; jt++) {
        const int j0 = jt * 128;
#pragma unroll
        for (int l = 0; l < 4; l++) {
            int e = tid + 256 * l;
            int j = e >> 3, dq = e & 7;
            int4 v = ((const int4*)mvh)[(size_t)(b * SS + j0 + j) * 48 + h * 8 + dq];
            *(int4*)&Vs[j * 72 + dq * 8] = v;
        }
        __syncthreads();
#pragma unroll
        for (int kc = 0; kc < 8; kc++) {
            const int kl = kc * 16;
            const int jg = j0 + kl + c2;
            const int cb = (jg >> 5) * 34 + (jg & 31);
            float2 v0 = *(const float2*)&P0[cb];
            float2 v1 = *(const float2*)&P8[cb];
            float2 v2 = *(const float2*)&P0[cb + 8];
            float2 v3 = *(const float2*)&P8[cb + 8];
            unsigned a0 = packh2(v0.x, v0.y);
            unsigned a1 = packh2(v1.x, v1.y);
            unsigned a2 = packh2(v2.x, v2.y);
            unsigned a3 = packh2(v3.x, v3.y);
            unsigned b0, b1;
            ldsm_x2t(b0, b1, kvB + ((kl + il) * 72 + 8 * w) * 2);
            asm volatile(
                "mma.sync.aligned.m16n8k16.row.col.f32.f16.f16.f32 "
                "{%0,%1,%2,%3}, {%4,%5,%6,%7}, {%8,%9}, {%0,%1,%2,%3};"
                : "+f"(acc[0]), "+f"(acc[1]), "+f"(acc[2]), "+f"(acc[3])
                : "r"(a0), "r"(a1), "r"(a2), "r"(a3), "r"(b0), "r"(b1));
        }
        __syncthreads();
    }
    {
        int dc = h * DDIM + 8 * w + c2;
        size_t o0 = (size_t)(b * SS + i0 + r4) * 768 + dc;
        size_t o1 = (size_t)(b * SS + i0 + r4 + 8) * 768 + dc;
        *(float2*)&out[o0] = make_float2(acc[0], acc[1]);
        *(float2*)&out[o1] = make_float2(acc[2], acc[3]);
    }
}

// ---------------- launch ----------------------------------------------------
extern "C" void kernel_launch(void* const* d_in, const int* in_sizes, int n_in,
                              void* d_out, int out_size) {
    const float* Q    = (const float*)d_in[0];
    const float* Kin  = (const float*)d_in[1];
    const float* V    = (const float*)d_in[2];
    const float* td   = (const float*)d_in[3];
    const int*   mask = (const int*)  d_in[4];
    const float* Wq   = (const float*)d_in[5];
    const float* Wk   = (const float*)d_in[6];
    const float* Wv   = (const float*)d_in[7];
    const float* dw_w = (const float*)d_in[8];
    const float* pw_w = (const float*)d_in[9];
    const float* sep_b= (const float*)d_in[10];
    const float* ck_W = (const float*)d_in[11];
    const float* ck_b = (const float*)d_in[12];
    const float* co_W = (const float*)d_in[13];
    const float* co_b = (const float*)d_in[14];
    const float* gammas=(const float*)d_in[15];
    float* out = (float*)d_out;

    float *mq, *co, *mkc, *tdsm;
    __half *Qh, *Kh, *Vh, *dwh, *WqT, *WkT, *WvT, *coT, *pwh, *mqh, *mkh, *mvh;
    cudaGetSymbolAddress((void**)&mq,  g_mq);
    cudaGetSymbolAddress((void**)&co,  g_co);
    cudaGetSymbolAddress((void**)&mkc, g_mkc);
    cudaGetSymbolAddress((void**)&tdsm,g_tdsm);
    cudaGetSymbolAddress((void**)&Qh,  g_Qh);
    cudaGetSymbolAddress((void**)&Kh,  g_Kh);
    cudaGetSymbolAddress((void**)&Vh,  g_Vh);
    cudaGetSymbolAddress((void**)&dwh, g_dwh);
    cudaGetSymbolAddress((void**)&WqT, g_WqT);
    cudaGetSymbolAddress((void**)&WkT, g_WkT);
    cudaGetSymbolAddress((void**)&WvT, g_WvT);
    cudaGetSymbolAddress((void**)&coT, g_coT);
    cudaGetSymbolAddress((void**)&pwh, g_pwh);
    cudaGetSymbolAddress((void**)&mqh, g_mqh);
    cudaGetSymbolAddress((void**)&mkh, g_mkh);
    cudaGetSymbolAddress((void**)&mvh, g_mvh);

    static int smem_set = 0;
    const int attn_smem = (TI * TPF + 4608 + 576 + 1056) * 4;   // 95104 B
    const int hgemm_smem = 3 * 2 * 128 * HPITCH * 2;            // 61440 B
    if (!smem_set) {
        cudaFuncSetAttribute(attn_kernel, cudaFuncAttributeMaxDynamicSharedMemorySize,
                             attn_smem);
        cudaFuncSetAttribute(hgemm, cudaFuncAttributeMaxDynamicSharedMemorySize,
                             hgemm_smem);
        smem_set = 1;
    }

    // ---- prep: converts + transposes + dwconv + tdsm in one launch ----
    PrepArgs pa;
    pa.Q = Q; pa.K = Kin; pa.V = V; pa.pw = pw_w;
    pa.Qh = Qh; pa.Kh = Kh; pa.Vh = Vh; pa.pwh = pwh;
    pa.Wq = Wq; pa.Wk = Wk; pa.Wv = Wv; pa.coW = co_W;
    pa.WqT = WqT; pa.WkT = WkT; pa.WvT = WvT; pa.coT = coT;
    pa.dw_w = dw_w; pa.dwh = dwh;
    pa.td = td; pa.mask = mask; pa.tdsm = tdsm;
    prep_kernel<<<22948, 256>>>(pa);

    // ---- 5 big GEMMs, one launch ----
    JobsH jh;
    jh.A[0] = Qh;  jh.B[0] = WqT; jh.bias[0] = nullptr; jh.C[0] = mq;     jh.Ch[0] = mqh;
    jh.A[1] = Kh;  jh.B[1] = WkT; jh.bias[1] = nullptr; jh.C[1] = nullptr;jh.Ch[1] = mkh;
    jh.A[2] = Vh;  jh.B[2] = WvT; jh.bias[2] = nullptr; jh.C[2] = nullptr;jh.Ch[2] = mvh;
    jh.A[3] = Vh;  jh.B[3] = coT; jh.bias[3] = co_b;    jh.C[3] = co;     jh.Ch[3] = nullptr;
    jh.A[4] = dwh; jh.B[4] = pwh; jh.bias[4] = sep_b;   jh.C[4] = mkc;    jh.Ch[4] = nullptr;
    hgemm<<<dim3(AHN / 128, NROWS / 128, 5), 256, hgemm_smem>>>(jh, NROWS, AHN, HIDN);

    attn_kernel<<<dim3(SS / TI, NH, BB), 256, attn_smem>>>(mqh, mkh, mvh, mask, tdsm,
                                                           gammas, out);
    ckconv<<<NROWS / 16, 256>>>(mkc, mq, ck_W, ck_b, co, out);
}